// round 3
// baseline (speedup 1.0000x reference)
#include <cuda_runtime.h>
#include <cstdint>
#include <cstddef>

#define T_STEPS 2048
#define B_SZ    128
#define H_SZ    200
#define IN_SZ   88
#define OUT_SZ  88
#define G4H     800      // 4*H
#define GBLOCKS 128      // persistent blocks (<=148 SMs -> all co-resident)

// ---------------- scratch (static device globals; no runtime allocation) ----
__device__ float    g_gx[(size_t)T_STEPS * G4H * B_SZ];   // [T][4H][B] gate pre-activations
__device__ float    g_y [(size_t)T_STEPS * B_SZ * H_SZ];  // layer outputs [T][B][H]
__device__ float    g_h [2 * B_SZ * H_SZ];                // double-buffered hidden state
__device__ unsigned g_bar;                                // global barrier counter

__device__ __forceinline__ unsigned ld_acq(const unsigned* p) {
    unsigned v;
    asm volatile("ld.global.acquire.gpu.u32 %0, [%1];" : "=r"(v) : "l"(p) : "memory");
    return v;
}

__device__ __forceinline__ float sigm(float x) {
    return __frcp_rn(1.0f + __expf(-x));
}
__device__ __forceinline__ float tanh_f(float x) {
    float e = __expf(-2.0f * fabsf(x));
    float r = (1.0f - e) * __frcp_rn(1.0f + e);
    return copysignf(r, x);
}

// ---------------- projection GEMM: out[t, r, b] (mode 0) or sigmoid out[t, b, r] (mode 1)
// A: [T][B][K] row-major, W: [R][K], block tile = 16 rows x 128 batch, 128 threads.
// x_sm rows padded to K+4 words -> warp-stride 204 == 4 mod 32: conflict-free LDS.128.
__global__ void proj_kernel(const float* __restrict__ A, const float* __restrict__ W,
                            const float* __restrict__ b1, const float* __restrict__ b2,
                            float* __restrict__ out, int K, int R, int mode)
{
    extern __shared__ float sm[];
    int KP = K + 4;                 // padded row stride (words), 4-word aligned
    float* x_sm = sm;               // [128][KP]
    float* w_sm = sm + 128 * KP;    // [16][K]

    int t   = blockIdx.y;
    int r0  = blockIdx.x * 16;
    int tid = threadIdx.x;
    int K4  = K >> 2;

    // stage A tile (coalesced float4 loads, padded smem rows)
    const float4* A4 = (const float4*)(A + (size_t)t * B_SZ * K);
    for (int i = tid; i < B_SZ * K4; i += 128) {
        int bb = i / K4, kk = i % K4;
        *((float4*)(x_sm + bb * KP) + kk) = A4[(size_t)bb * K4 + kk];
    }

    // stage 16 weight rows (zero-fill OOB rows)
    float4* ws4 = (float4*)w_sm;
    for (int i = tid; i < 16 * K4; i += 128) {
        int r = i / K4, kk = i % K4, rg = r0 + r;
        float4 v = make_float4(0.f, 0.f, 0.f, 0.f);
        if (rg < R) v = ((const float4*)(W + (size_t)rg * K))[kk];
        ws4[i] = v;
    }
    __syncthreads();

    int b = tid;  // one thread per batch element
    float acc[16];
#pragma unroll
    for (int r = 0; r < 16; r++) {
        int rg = r0 + r;
        acc[r] = (rg < R) ? (b1[rg] + (b2 ? b2[rg] : 0.f)) : 0.f;
    }

    const float4* xrow = (const float4*)(x_sm + (size_t)b * KP);
#pragma unroll 2
    for (int kk = 0; kk < K4; kk++) {
        float4 xv = xrow[kk];
#pragma unroll
        for (int r = 0; r < 16; r++) {
            float4 wv = ws4[r * K4 + kk];
            acc[r] += xv.x * wv.x + xv.y * wv.y + xv.z * wv.z + xv.w * wv.w;
        }
    }

    if (mode == 0) {
#pragma unroll
        for (int r = 0; r < 16; r++) {
            int rg = r0 + r;
            if (rg < R) out[((size_t)t * R + rg) * B_SZ + b] = acc[r];
        }
    } else {
#pragma unroll
        for (int r = 0; r < 16; r++) {
            int rg = r0 + r;
            if (rg < R) out[((size_t)t * B_SZ + b) * R + rg] = sigm(acc[r]);
        }
    }
}

// ---------------- persistent LSTM recurrence -------------------------------
// Grid: 128 blocks = 16 batch-groups (8 batches) x 8 j-groups (25 hidden units).
// Thread (tid<200): b = tid&7, u = tid>>3 -> owns (batch bg*8+b, unit jg*25+u),
// computes all 4 gates, keeps c in a register across all 2048 steps.
__global__ void lstm_kernel(const float* __restrict__ gx,   // [T][4H][B]
                            const float* __restrict__ whh,  // [4H][H]
                            float* __restrict__ y,          // [T][B][H]
                            float* __restrict__ hn, float* __restrict__ cn)
{
    extern __shared__ float sm[];
    float* w_sm = sm;            // [4][25][200] = 20000 floats (80 KB)
    float* h_sm = sm + 20000;    // [8][204] padded (conflict-free)

    int tid = threadIdx.x;
    int bg = blockIdx.x >> 3, jg = blockIdx.x & 7;

    // stage this block's weight slice once (coalesced over k)
    for (int i = tid; i < 20000; i += 256) {
        int g = i / 5000, rem = i % 5000, u = rem / 200, k = rem % 200;
        w_sm[i] = whh[(size_t)(g * 200 + jg * 25 + u) * H_SZ + k];
    }

    bool active = tid < 200;
    int b = tid & 7, u = tid >> 3;
    int j = jg * 25 + u, bglob = bg * 8 + b;
    float c = 0.f;

    const float4* wi4 = (const float4*)(w_sm +     0 + u * 200);
    const float4* wf4 = (const float4*)(w_sm +  5000 + u * 200);
    const float4* wg4 = (const float4*)(w_sm + 10000 + u * 200);
    const float4* wo4 = (const float4*)(w_sm + 15000 + u * 200);
    __syncthreads();

    for (int t = 0; t < T_STEPS; t++) {
        const float* hsrc = g_h + (t & 1) * (B_SZ * H_SZ);
        float*       hdst = g_h + ((t + 1) & 1) * (B_SZ * H_SZ);

        // issue gx loads early (DRAM latency overlapped with h staging)
        float ai = 0.f, af = 0.f, ag = 0.f, ao = 0.f;
        if (active) {
            size_t base = ((size_t)t * G4H + j) * B_SZ + bglob;
            ai = gx[base];
            af = gx[base + 200 * B_SZ];
            ag = gx[base + 400 * B_SZ];
            ao = gx[base + 600 * B_SZ];
        }

        // stage h for this block's 8 batches (bypass L1 — written by other SMs)
        for (int i = tid; i < 400; i += 256) {
            int bb = i / 50, kk = i % 50;
            float4 v = __ldcg((const float4*)(hsrc + (size_t)(bg * 8 + bb) * H_SZ) + kk);
            *((float4*)(h_sm + bb * 204) + kk) = v;
        }
        __syncthreads();

        if (active) {
            const float4* h4 = (const float4*)(h_sm + b * 204);
#pragma unroll
            for (int kk = 0; kk < 50; kk++) {
                float4 hv = h4[kk];
                float4 a = wi4[kk]; ai += hv.x * a.x + hv.y * a.y + hv.z * a.z + hv.w * a.w;
                float4 f = wf4[kk]; af += hv.x * f.x + hv.y * f.y + hv.z * f.z + hv.w * f.w;
                float4 g = wg4[kk]; ag += hv.x * g.x + hv.y * g.y + hv.z * g.z + hv.w * g.w;
                float4 o = wo4[kk]; ao += hv.x * o.x + hv.y * o.y + hv.z * o.z + hv.w * o.w;
            }
            float I = sigm(ai), F = sigm(af), G = tanh_f(ag), O = sigm(ao);
            c = F * c + I * G;
            float h = O * tanh_f(c);
            __stcg(hdst + (size_t)bglob * H_SZ + j, h);
            y[((size_t)t * B_SZ + bglob) * H_SZ + j] = h;
            if (t == T_STEPS - 1) {
                hn[bglob * H_SZ + j] = h;
                cn[bglob * H_SZ + j] = c;
            }
        }

        // global barrier: fence all writes, arrive, spin (with backoff) on counter
        __threadfence();
        __syncthreads();
        if (tid == 0) {
            atomicAdd(&g_bar, 1u);
            unsigned target = (unsigned)(t + 1) * GBLOCKS;
            while (ld_acq(&g_bar) < target) { __nanosleep(40); }
        }
        __syncthreads();
    }
}

// ---------------- launch ----------------------------------------------------
extern "C" void kernel_launch(void* const* d_in, const int* in_sizes, int n_in,
                              void* d_out, int out_size)
{
    const float* x     = (const float*)d_in[0];
    const float* w_ih0 = (const float*)d_in[1];
    const float* w_hh0 = (const float*)d_in[2];
    const float* b_ih0 = (const float*)d_in[3];
    const float* b_hh0 = (const float*)d_in[4];
    const float* w_ih1 = (const float*)d_in[5];
    const float* w_hh1 = (const float*)d_in[6];
    const float* b_ih1 = (const float*)d_in[7];
    const float* b_hh1 = (const float*)d_in[8];
    const float* w_fc  = (const float*)d_in[9];
    const float* b_fc  = (const float*)d_in[10];

    float* out = (float*)d_out;
    float* hn  = out + (size_t)T_STEPS * B_SZ * OUT_SZ;   // [2][B][H]
    float* cn  = hn + 2 * B_SZ * H_SZ;                    // [2][B][H]

    void *gx_p, *y_p, *h_p, *bar_p;
    cudaGetSymbolAddress(&gx_p, g_gx);
    cudaGetSymbolAddress(&y_p,  g_y);
    cudaGetSymbolAddress(&h_p,  g_h);
    cudaGetSymbolAddress(&bar_p, g_bar);
    float* gxb = (float*)gx_p;
    float* yb  = (float*)y_p;

    const int proj_smem_max = (128 * 204 + 16 * 200) * 4;  // K<=200 padded
    const int lstm_smem     = (20000 + 8 * 204) * 4;
    cudaFuncSetAttribute(proj_kernel, cudaFuncAttributeMaxDynamicSharedMemorySize, proj_smem_max);
    cudaFuncSetAttribute(lstm_kernel, cudaFuncAttributeMaxDynamicSharedMemorySize, lstm_smem);

    // ----- layer 0 -----
    proj_kernel<<<dim3(50, T_STEPS), 128, (128 * (IN_SZ + 4) + 16 * IN_SZ) * 4>>>(
        x, w_ih0, b_ih0, b_hh0, gxb, IN_SZ, G4H, 0);
    cudaMemsetAsync(h_p, 0, 2 * B_SZ * H_SZ * sizeof(float));
    cudaMemsetAsync(bar_p, 0, sizeof(unsigned));
    lstm_kernel<<<GBLOCKS, 256, lstm_smem>>>(gxb, w_hh0, yb, hn, cn);

    // ----- layer 1 -----
    proj_kernel<<<dim3(50, T_STEPS), 128, (128 * (H_SZ + 4) + 16 * H_SZ) * 4>>>(
        yb, w_ih1, b_ih1, b_hh1, gxb, H_SZ, G4H, 0);
    cudaMemsetAsync(h_p, 0, 2 * B_SZ * H_SZ * sizeof(float));
    cudaMemsetAsync(bar_p, 0, sizeof(unsigned));
    lstm_kernel<<<GBLOCKS, 256, lstm_smem>>>(gxb, w_hh1, yb,
                                             hn + B_SZ * H_SZ, cn + B_SZ * H_SZ);

    // ----- FC head -----
    proj_kernel<<<dim3(6, T_STEPS), 128, (128 * (H_SZ + 4) + 16 * H_SZ) * 4>>>(
        yb, w_fc, b_fc, nullptr, out, H_SZ, OUT_SZ, 1);
}

// round 5
// speedup vs baseline: 1.1400x; 1.1400x over previous
#include <cuda_runtime.h>
#include <cstdint>
#include <cstddef>

#define T_STEPS 2048
#define B_SZ    128
#define H_SZ    200
#define IN_SZ   88
#define OUT_SZ  88
#define G4H     800
#define CL_N    8        // CTAs per cluster (one batch-group)

// ---------------- scratch (static device globals) ---------------------------
__device__ float g_gx[(size_t)T_STEPS * G4H * B_SZ];   // [T][4H][B]
__device__ float g_y [(size_t)T_STEPS * B_SZ * H_SZ];  // [T][B][H]

__device__ __forceinline__ float sigm(float x) {
    return __frcp_rn(1.0f + __expf(-x));
}
__device__ __forceinline__ float tanh_f(float x) {
    float e = __expf(-2.0f * fabsf(x));
    float r = (1.0f - e) * __frcp_rn(1.0f + e);
    return copysignf(r, x);
}
__device__ __forceinline__ float2 unpack2(unsigned long long v) {
    float2 r;
    asm("mov.b64 {%0, %1}, %2;" : "=f"(r.x), "=f"(r.y) : "l"(v));
    return r;
}
#define FMA2(acc, a, b) \
    asm("fma.rn.f32x2 %0, %1, %2, %0;" : "+l"(acc) : "l"(a), "l"(b))

// ---------------- projection GEMM -------------------------------------------
// out[t, r, b] (mode 0) or sigmoid out[t, b, r] (mode 1)
// A: [T][B][K] row-major, W: [R][K]. 16 rows x 128 batch per block, 128 thr.
// x read from global (L1/L2, 16-way register reuse); w in smem (broadcast
// LDS within 8-lane groups). Packed f32x2 FMA.
__global__ void proj_kernel(const float* __restrict__ A, const float* __restrict__ W,
                            const float* __restrict__ b1, const float* __restrict__ b2,
                            float* __restrict__ out, int K, int R, int mode)
{
    __shared__ float w_sm[16 * H_SZ];   // max K = 200

    int t   = blockIdx.y;
    int r0  = blockIdx.x * 16;
    int tid = threadIdx.x;
    int K4  = K >> 2;

    for (int i = tid; i < 16 * K4; i += 128) {
        int r = i / K4, kk = i % K4, rg = r0 + r;
        float4 v = make_float4(0.f, 0.f, 0.f, 0.f);
        if (rg < R) v = ((const float4*)(W + (size_t)rg * K))[kk];
        ((float4*)w_sm)[i] = v;
    }
    __syncthreads();

    int b = tid;
    unsigned long long acc[16];
#pragma unroll
    for (int r = 0; r < 16; r++) acc[r] = 0ULL;

    const ulonglong2* xrow = (const ulonglong2*)(A + ((size_t)t * B_SZ + b) * K);
#pragma unroll 2
    for (int kk = 0; kk < K4; kk++) {
        ulonglong2 xv = __ldg(xrow + kk);
#pragma unroll
        for (int r = 0; r < 16; r++) {
            ulonglong2 wv = *((const ulonglong2*)(w_sm + r * K) + kk);
            FMA2(acc[r], xv.x, wv.x);
            FMA2(acc[r], xv.y, wv.y);
        }
    }

    if (mode == 0) {
#pragma unroll
        for (int r = 0; r < 16; r++) {
            int rg = r0 + r;
            if (rg < R) {
                float2 p = unpack2(acc[r]);
                out[((size_t)t * R + rg) * B_SZ + b] =
                    p.x + p.y + b1[rg] + b2[rg];
            }
        }
    } else {
#pragma unroll
        for (int r = 0; r < 16; r++) {
            int rg = r0 + r;
            if (rg < R) {
                float2 p = unpack2(acc[r]);
                out[((size_t)t * B_SZ + b) * R + rg] = sigm(p.x + p.y + b1[rg]);
            }
        }
    }
}

// ---------------- persistent LSTM recurrence: cluster version ---------------
// Grid (8, 16), cluster (8,1,1). Cluster = one batch-group of 8 batches;
// CTA rank jg owns 25 hidden units. Thread (tid<200): b=tid&7, u=tid>>3.
// h exchanged via DSMEM broadcast stores + one cluster barrier per step.
// smem: w slice [4][25][200] (80 KB) + h double buffer [2][8][204].
#define HS_OFF   20000
#define HS_BUF   (8 * 204)
__global__ void __cluster_dims__(CL_N, 1, 1)
lstm_kernel(const float* __restrict__ gx,   // [T][4H][B]
            const float* __restrict__ whh,  // [4H][H]
            float* __restrict__ y,          // [T][B][H]
            float* __restrict__ hn, float* __restrict__ cn)
{
    extern __shared__ float sm[];
    float* w_sm = sm;                       // 20000 floats

    int tid = threadIdx.x;
    int jg  = blockIdx.x;                   // cluster rank
    int bg  = blockIdx.y;

    // stage this CTA's weight slice (coalesced over k)
    for (int i = tid; i < 20000; i += 256) {
        int g = i / 5000, rem = i % 5000, u = rem / 200, k = rem % 200;
        w_sm[i] = whh[(size_t)(g * 200 + jg * 25 + u) * H_SZ + k];
    }
    // zero h double-buffer
    for (int i = tid; i < 2 * HS_BUF; i += 256) sm[HS_OFF + i] = 0.f;
    __syncthreads();
    // all CTAs initialized before any remote store can land
    asm volatile("barrier.cluster.arrive.aligned;" ::: "memory");
    asm volatile("barrier.cluster.wait.aligned;"   ::: "memory");

    unsigned smem_u32;
    {
        unsigned long long tmp;
        asm("cvta.to.shared.u64 %0, %1;" : "=l"(tmp) : "l"(sm));
        smem_u32 = (unsigned)tmp;
    }

    bool active = tid < 200;
    int b = tid & 7, u = tid >> 3;
    int j = jg * 25 + u, bglob = bg * 8 + b;
    float c = 0.f;

    const ulonglong2* wi2 = (const ulonglong2*)(w_sm +     0 + u * 200);
    const ulonglong2* wf2 = (const ulonglong2*)(w_sm +  5000 + u * 200);
    const ulonglong2* wg2 = (const ulonglong2*)(w_sm + 10000 + u * 200);
    const ulonglong2* wo2 = (const ulonglong2*)(w_sm + 15000 + u * 200);

    // preload gx for t = 0
    float gi = 0.f, gf = 0.f, gg = 0.f, go = 0.f;
    if (active) {
        size_t base = (size_t)j * B_SZ + bglob;
        gi = gx[base];
        gf = gx[base + 200 * B_SZ];
        gg = gx[base + 400 * B_SZ];
        go = gx[base + 600 * B_SZ];
    }

    for (int t = 0; t < T_STEPS; t++) {
        // prefetch next step's gx (hidden under the dot product)
        float ni = 0.f, nf = 0.f, ng = 0.f, no = 0.f;
        if (active && t + 1 < T_STEPS) {
            size_t base = ((size_t)(t + 1) * G4H + j) * B_SZ + bglob;
            ni = gx[base];
            nf = gx[base + 200 * B_SZ];
            ng = gx[base + 400 * B_SZ];
            no = gx[base + 600 * B_SZ];
        }

        if (active) {
            const ulonglong2* h2 =
                (const ulonglong2*)(sm + HS_OFF + (t & 1) * HS_BUF + b * 204);
            unsigned long long ai = 0ULL, af = 0ULL, ag = 0ULL, ao = 0ULL;
#pragma unroll
            for (int kk = 0; kk < 50; kk++) {
                ulonglong2 hv = h2[kk];
                ulonglong2 w;
                w = wi2[kk]; FMA2(ai, hv.x, w.x); FMA2(ai, hv.y, w.y);
                w = wf2[kk]; FMA2(af, hv.x, w.x); FMA2(af, hv.y, w.y);
                w = wg2[kk]; FMA2(ag, hv.x, w.x); FMA2(ag, hv.y, w.y);
                w = wo2[kk]; FMA2(ao, hv.x, w.x); FMA2(ao, hv.y, w.y);
            }
            float2 pi = unpack2(ai), pf = unpack2(af);
            float2 pg = unpack2(ag), po = unpack2(ao);
            float I = sigm(pi.x + pi.y + gi);
            float F = sigm(pf.x + pf.y + gf);
            float G = tanh_f(pg.x + pg.y + gg);
            float O = sigm(po.x + po.y + go);
            c = F * c + I * G;
            float h = O * tanh_f(c);

            y[((size_t)t * B_SZ + bglob) * H_SZ + j] = h;
            if (t == T_STEPS - 1) {
                hn[bglob * H_SZ + j] = h;
                cn[bglob * H_SZ + j] = c;
            }

            // broadcast h into every cluster CTA's next-step buffer
            unsigned loc = smem_u32 +
                (HS_OFF + ((t + 1) & 1) * HS_BUF + b * 204 + j) * 4u;
#pragma unroll
            for (int r = 0; r < CL_N; r++) {
                unsigned rem;
                asm("mapa.shared::cluster.u32 %0, %1, %2;"
                    : "=r"(rem) : "r"(loc), "r"(r));
                asm volatile("st.shared::cluster.f32 [%0], %1;"
                             :: "r"(rem), "f"(h) : "memory");
            }
        }

        // one cluster barrier per step (release/acquire orders DSMEM stores)
        asm volatile("barrier.cluster.arrive.aligned;" ::: "memory");
        asm volatile("barrier.cluster.wait.aligned;"   ::: "memory");

        gi = ni; gf = nf; gg = ng; go = no;
    }
}

// ---------------- launch ----------------------------------------------------
extern "C" void kernel_launch(void* const* d_in, const int* in_sizes, int n_in,
                              void* d_out, int out_size)
{
    const float* x     = (const float*)d_in[0];
    const float* w_ih0 = (const float*)d_in[1];
    const float* w_hh0 = (const float*)d_in[2];
    const float* b_ih0 = (const float*)d_in[3];
    const float* b_hh0 = (const float*)d_in[4];
    const float* w_ih1 = (const float*)d_in[5];
    const float* w_hh1 = (const float*)d_in[6];
    const float* b_ih1 = (const float*)d_in[7];
    const float* b_hh1 = (const float*)d_in[8];
    const float* w_fc  = (const float*)d_in[9];
    const float* b_fc  = (const float*)d_in[10];

    float* out = (float*)d_out;
    float* hn  = out + (size_t)T_STEPS * B_SZ * OUT_SZ;   // [2][B][H]
    float* cn  = hn + 2 * B_SZ * H_SZ;

    void *gx_p, *y_p;
    cudaGetSymbolAddress(&gx_p, g_gx);
    cudaGetSymbolAddress(&y_p,  g_y);
    float* gxb = (float*)gx_p;
    float* yb  = (float*)y_p;

    const int lstm_smem = (HS_OFF + 2 * HS_BUF) * 4;
    cudaFuncSetAttribute(lstm_kernel,
                         cudaFuncAttributeMaxDynamicSharedMemorySize, lstm_smem);

    dim3 lstm_grid(CL_N, 16);

    // ----- layer 0 -----
    proj_kernel<<<dim3(50, T_STEPS), 128>>>(x, w_ih0, b_ih0, b_hh0,
                                            gxb, IN_SZ, G4H, 0);
    lstm_kernel<<<lstm_grid, 256, lstm_smem>>>(gxb, w_hh0, yb, hn, cn);

    // ----- layer 1 -----
    proj_kernel<<<dim3(50, T_STEPS), 128>>>(yb, w_ih1, b_ih1, b_hh1,
                                            gxb, H_SZ, G4H, 0);
    lstm_kernel<<<lstm_grid, 256, lstm_smem>>>(gxb, w_hh1, yb,
                                               hn + B_SZ * H_SZ,
                                               cn + B_SZ * H_SZ);

    // ----- FC head -----
    proj_kernel<<<dim3(6, T_STEPS), 128>>>(yb, w_fc, b_fc, nullptr,
                                           out, H_SZ, OUT_SZ, 1);
}